// round 1
// baseline (speedup 1.0000x reference)
#include <cuda_runtime.h>
#include <math.h>
#include <stdint.h>

#define B_   256
#define S1_  512
#define S2_  64
#define H_   768
#define OPC_ 64
#define OT_  128            // OPC + S2
#define NEGV (-1e12f)

// ---------------- scratch (device globals: no runtime allocation allowed) ---
__device__ float g_lc  [B_ * 2 * H_];
__device__ float g_gA  [B_ * H_];
__device__ float g_gB  [B_ * H_];
__device__ float g_gC  [B_ * H_];
__device__ float g_gD  [B_ * H_];
__device__ float g_node[B_ * H_];
__device__ float g_P1  [B_ * H_];
__device__ float g_P2  [(size_t)B_ * S1_ * H_];      // 402 MB
__device__ float g_eng [B_ * S1_];
__device__ float g_ctx [B_ * H_];
__device__ float g_leaf[B_ * 2 * H_];
__device__ float g_Q1  [B_ * H_];
__device__ float g_Q2c [OPC_ * H_];
__device__ float g_Q2v [(size_t)B_ * S2_ * H_];      // 48 MB

// ---------------- generic tiled SGEMM: C = A[MxK] * B[KxN] (+bias) ----------
// 128x128 tile, BK=16, 256 threads, 8x8 per thread. N must be multiple of 128.
__global__ __launch_bounds__(256) void sgemm_k(
    const float* __restrict__ A, const float* __restrict__ Bm,
    const float* __restrict__ bias, float* __restrict__ C,
    int M, int N, int K)
{
    __shared__ float As[16][128];
    __shared__ float Bs[16][132];

    const int tid = threadIdx.x;
    const int bm = blockIdx.y * 128;
    const int bn = blockIdx.x * 128;
    const int tx = tid & 15;         // n-direction (8 cols)
    const int ty = tid >> 4;         // m-direction (8 rows)

    float acc[8][8];
#pragma unroll
    for (int i = 0; i < 8; i++)
#pragma unroll
        for (int j = 0; j < 8; j++) acc[i][j] = 0.f;

    // A tile loader: row = tid>>1 (0..127), cols (tid&1)*8 .. +7
    const int a_row = tid >> 1;
    const int a_col = (tid & 1) * 8;
    const bool a_ok = (bm + a_row) < M;
    const float* Aptr = A + (size_t)(bm + a_row) * K + a_col;

    // B tile loader: row = tid>>4 (0..15), cols (tid&15)*8 .. +7
    const int b_row = tid >> 4;
    const int b_col = (tid & 15) * 8;
    const float* Bptr = Bm + (size_t)b_row * N + bn + b_col;

    for (int k0 = 0; k0 < K; k0 += 16) {
        float4 a0, a1;
        if (a_ok) {
            a0 = *(const float4*)(Aptr);
            a1 = *(const float4*)(Aptr + 4);
        } else {
            a0 = make_float4(0.f, 0.f, 0.f, 0.f);
            a1 = a0;
        }
        float4 b0 = *(const float4*)(Bptr);
        float4 b1 = *(const float4*)(Bptr + 4);

        As[a_col + 0][a_row] = a0.x;
        As[a_col + 1][a_row] = a0.y;
        As[a_col + 2][a_row] = a0.z;
        As[a_col + 3][a_row] = a0.w;
        As[a_col + 4][a_row] = a1.x;
        As[a_col + 5][a_row] = a1.y;
        As[a_col + 6][a_row] = a1.z;
        As[a_col + 7][a_row] = a1.w;
        *(float4*)&Bs[b_row][b_col]     = b0;
        *(float4*)&Bs[b_row][b_col + 4] = b1;
        __syncthreads();

#pragma unroll
        for (int k = 0; k < 16; k++) {
            float a[8], b[8];
            *(float4*)(a)     = *(const float4*)&As[k][ty * 8];
            *(float4*)(a + 4) = *(const float4*)&As[k][ty * 8 + 4];
            *(float4*)(b)     = *(const float4*)&Bs[k][tx * 8];
            *(float4*)(b + 4) = *(const float4*)&Bs[k][tx * 8 + 4];
#pragma unroll
            for (int i = 0; i < 8; i++)
#pragma unroll
                for (int j = 0; j < 8; j++)
                    acc[i][j] = fmaf(a[i], b[j], acc[i][j]);
        }
        __syncthreads();

        Aptr += 16;
        Bptr += (size_t)16 * N;
    }

    float bi[8];
#pragma unroll
    for (int j = 0; j < 8; j++) bi[j] = bias ? bias[bn + tx * 8 + j] : 0.f;

#pragma unroll
    for (int i = 0; i < 8; i++) {
        int r = bm + ty * 8 + i;
        if (r < M) {
            float* Cr = C + (size_t)r * N + bn + tx * 8;
            float4 v0 = make_float4(acc[i][0] + bi[0], acc[i][1] + bi[1],
                                    acc[i][2] + bi[2], acc[i][3] + bi[3]);
            float4 v1 = make_float4(acc[i][4] + bi[4], acc[i][5] + bi[5],
                                    acc[i][6] + bi[6], acc[i][7] + bi[7]);
            *(float4*)Cr       = v0;
            *(float4*)(Cr + 4) = v1;
        }
    }
}

// ---------------- small helper kernels --------------------------------------
__device__ __forceinline__ float sigmoidf_(float x) { return 1.f / (1.f + expf(-x)); }

// out[b, 0:H] = x[b], out[b, H:2H] = y[b]
__global__ void concat2_k(const float* __restrict__ x, const float* __restrict__ y,
                          float* __restrict__ out)
{
    int i = blockIdx.x * blockDim.x + threadIdx.x;
    if (i >= B_ * H_) return;
    int b = i / H_, h = i % H_;
    out[(size_t)b * 2 * H_ + h]      = x[i];
    out[(size_t)b * 2 * H_ + H_ + h] = y[i];
}

__global__ void combine_node_k(const int* __restrict__ has_left)
{
    int i = blockIdx.x * blockDim.x + threadIdx.x;
    if (i >= B_ * H_) return;
    int b = i / H_;
    float v;
    if (has_left[b])
        v = tanhf(g_gC[i]) * sigmoidf_(g_gD[i]);
    else
        v = tanhf(g_gA[i]) * sigmoidf_(g_gB[i]);
    g_node[i] = v;
}

// energy[b,s] = mask ? NEG : sum_h v[h] * tanh(P1[b,h] + P2[b,s,h])
__global__ void energy_k(const float* __restrict__ vattn, const int* __restrict__ smask)
{
    int warp = (blockIdx.x * blockDim.x + threadIdx.x) >> 5;
    if (warp >= B_ * S1_) return;
    int lane = threadIdx.x & 31;
    int b = warp / S1_;
    const float* p1 = g_P1 + (size_t)b * H_;
    const float* p2 = g_P2 + (size_t)warp * H_;
    float acc = 0.f;
    for (int h = lane; h < H_; h += 32)
        acc += vattn[h] * tanhf(p1[h] + p2[h]);
#pragma unroll
    for (int o = 16; o; o >>= 1) acc += __shfl_xor_sync(0xFFFFFFFFu, acc, o);
    if (lane == 0) g_eng[warp] = smask[warp] ? NEGV : acc;
}

// in-place softmax over S1 per batch row (block = 256 threads, 2 elems/thread)
__global__ void softmax_k()
{
    __shared__ float red[256];
    int b = blockIdx.x, t = threadIdx.x;
    float* e = g_eng + (size_t)b * S1_;
    float x0 = e[t], x1 = e[t + 256];
    red[t] = fmaxf(x0, x1);
    __syncthreads();
    for (int s = 128; s > 0; s >>= 1) {
        if (t < s) red[t] = fmaxf(red[t], red[t + s]);
        __syncthreads();
    }
    float m = red[0];
    __syncthreads();
    float e0 = expf(x0 - m), e1 = expf(x1 - m);
    red[t] = e0 + e1;
    __syncthreads();
    for (int s = 128; s > 0; s >>= 1) {
        if (t < s) red[t] += red[t + s];
        __syncthreads();
    }
    float inv = 1.f / red[0];
    e[t] = e0 * inv;
    e[t + 256] = e1 * inv;
}

// context[b,h] = sum_s attn[b,s] * enc[b,s,h]   (block per b, 768 threads)
__global__ void context_k(const float* __restrict__ enc)
{
    int b = blockIdx.x, h = threadIdx.x;
    const float* a = g_eng + (size_t)b * S1_;
    const float* e = enc + (size_t)b * S1_ * H_ + h;
    float acc = 0.f;
#pragma unroll 8
    for (int s = 0; s < S1_; s++)
        acc = fmaf(__ldg(a + s), __ldg(e + (size_t)s * H_), acc);
    g_ctx[(size_t)b * H_ + h] = acc;
}

// score[b,o] = mask ? NEG : sum_h v[h] * tanh(Q1[b,h] + Q2[b,o,h])
__global__ void score_k(const float* __restrict__ vsc, const int* __restrict__ cmask,
                        float* __restrict__ out)
{
    int idx = (blockIdx.x * blockDim.x + threadIdx.x) >> 5;
    if (idx >= B_ * OT_) return;
    int lane = threadIdx.x & 31;
    int b = idx / OT_, o = idx % OT_;
    const float* q1 = g_Q1 + (size_t)b * H_;
    const float* q2 = (o < OPC_) ? (g_Q2c + (size_t)o * H_)
                                 : (g_Q2v + ((size_t)b * S2_ + (o - OPC_)) * H_);
    float acc = 0.f;
    for (int h = lane; h < H_; h += 32)
        acc += vsc[h] * tanhf(q1[h] + q2[h]);
#pragma unroll
    for (int o2 = 16; o2; o2 >>= 1) acc += __shfl_xor_sync(0xFFFFFFFFu, acc, o2);
    if (lane == 0) out[idx] = cmask[idx] ? NEGV : acc;
}

__global__ void copy_k(const float* __restrict__ src, float* __restrict__ dst, int n)
{
    int i = blockIdx.x * blockDim.x + threadIdx.x;
    if (i < n) dst[i] = src[i];
}

// emb_all[b,o,h]: o<OPC -> emb_op_const[o,h], else var_pades[b,o-OPC,h]; float4
__global__ void emb_all_k(const float* __restrict__ opc, const float* __restrict__ var,
                          float* __restrict__ dst)
{
    size_t i = (size_t)blockIdx.x * blockDim.x + threadIdx.x;   // float4 index
    const size_t total = (size_t)B_ * OT_ * H_ / 4;
    if (i >= total) return;
    size_t elem = i * 4;
    int h = (int)(elem % H_);
    size_t bo = elem / H_;
    int o = (int)(bo % OT_);
    int b = (int)(bo / OT_);
    float4 v;
    if (o < OPC_)
        v = *(const float4*)(opc + (size_t)o * H_ + h);
    else
        v = *(const float4*)(var + ((size_t)b * S2_ + (o - OPC_)) * H_ + h);
    ((float4*)dst)[i] = v;
}

// ---------------- launch -----------------------------------------------------
static inline void gemm(const float* A, const float* B, const float* bias, float* C,
                        int M, int N, int K)
{
    dim3 grid(N / 128, (M + 127) / 128);
    sgemm_k<<<grid, 256>>>(A, B, bias, C, M, N, K);
}

extern "C" void kernel_launch(void* const* d_in, const int* in_sizes, int n_in,
                              void* d_out, int out_size)
{
    (void)in_sizes; (void)n_in; (void)out_size;
    const float* current = (const float*)d_in[0];
    const float* left    = (const float*)d_in[1];
    const float* enc     = (const float*)d_in[2];
    const float* var     = (const float*)d_in[3];
    const float* opc     = (const float*)d_in[4];
    const float* W_l     = (const float*)d_in[5];
    const float* b_l     = (const float*)d_in[6];
    const float* W_lg    = (const float*)d_in[7];
    const float* b_lg    = (const float*)d_in[8];
    const float* W_r     = (const float*)d_in[9];
    const float* b_r     = (const float*)d_in[10];
    const float* W_rg    = (const float*)d_in[11];
    const float* b_rg    = (const float*)d_in[12];
    const float* W_attn  = (const float*)d_in[13];
    const float* b_attn  = (const float*)d_in[14];
    const float* v_attn  = (const float*)d_in[15];
    const float* W_score = (const float*)d_in[16];
    const float* b_score = (const float*)d_in[17];
    const float* v_score = (const float*)d_in[18];
    const int*   has_left = (const int*)d_in[19];
    const int*   smask    = (const int*)d_in[20];
    const int*   cmask    = (const int*)d_in[21];

    float *lc, *gA, *gB, *gC, *gD, *node, *P1, *P2, *ctx, *leaf, *Q1, *Q2c, *Q2v;
    cudaGetSymbolAddress((void**)&lc,   g_lc);
    cudaGetSymbolAddress((void**)&gA,   g_gA);
    cudaGetSymbolAddress((void**)&gB,   g_gB);
    cudaGetSymbolAddress((void**)&gC,   g_gC);
    cudaGetSymbolAddress((void**)&gD,   g_gD);
    cudaGetSymbolAddress((void**)&node, g_node);
    cudaGetSymbolAddress((void**)&P1,   g_P1);
    cudaGetSymbolAddress((void**)&P2,   g_P2);
    cudaGetSymbolAddress((void**)&ctx,  g_ctx);
    cudaGetSymbolAddress((void**)&leaf, g_leaf);
    cudaGetSymbolAddress((void**)&Q1,   g_Q1);
    cudaGetSymbolAddress((void**)&Q2c,  g_Q2c);
    cudaGetSymbolAddress((void**)&Q2v,  g_Q2v);

    float* out       = (float*)d_out;
    float* out_score = out;                         // [B, 128]
    float* out_node  = out_score + B_ * OT_;        // [B, 1, H]
    float* out_ctx   = out_node + B_ * H_;          // [B, 1, H]
    float* out_emb   = out_ctx + B_ * H_;           // [B, 128, H]

    const int BH = B_ * H_;

    // --- node ---
    concat2_k<<<(BH + 255) / 256, 256>>>(left, current, lc);
    gemm(current, W_l,  b_l,  gA, B_, H_, H_);
    gemm(current, W_lg, b_lg, gB, B_, H_, H_);
    gemm(lc,      W_r,  b_r,  gC, B_, H_, 2 * H_);
    gemm(lc,      W_rg, b_rg, gD, B_, H_, 2 * H_);
    combine_node_k<<<(BH + 255) / 256, 256>>>(has_left);

    // --- attention ---
    gemm(node, W_attn, b_attn, P1, B_, H_, H_);                      // hid part + bias
    gemm(enc,  W_attn + (size_t)H_ * H_, nullptr, P2,
         B_ * S1_, H_, H_);                                          // enc part (big)
    {
        int rows = B_ * S1_;                       // one warp per row
        int blocks = (rows * 32 + 255) / 256;
        energy_k<<<blocks, 256>>>(v_attn, smask);
    }
    softmax_k<<<B_, 256>>>();
    context_k<<<B_, H_>>>(enc);

    // --- leaf score ---
    concat2_k<<<(BH + 255) / 256, 256>>>(node, ctx, leaf);
    gemm(leaf, W_score, b_score, Q1, B_, H_, 2 * H_);
    gemm(opc,  W_score + (size_t)2 * H_ * H_, nullptr, Q2c, OPC_, H_, H_);
    gemm(var,  W_score + (size_t)2 * H_ * H_, nullptr, Q2v, B_ * S2_, H_, H_);
    {
        int rows = B_ * OT_;
        int blocks = (rows * 32 + 255) / 256;
        score_k<<<blocks, 256>>>(v_score, cmask, out_score);
    }

    // --- remaining outputs ---
    copy_k<<<(BH + 255) / 256, 256>>>(node, out_node, BH);
    copy_k<<<(BH + 255) / 256, 256>>>(ctx,  out_ctx,  BH);
    {
        size_t total4 = (size_t)B_ * OT_ * H_ / 4;
        emb_all_k<<<(unsigned)((total4 + 255) / 256), 256>>>(opc, var, out_emb);
    }
}